// round 1
// baseline (speedup 1.0000x reference)
#include <cuda_runtime.h>
#include <math.h>

// Problem constants (fixed by the dataset)
#define NF 100000   // firms
#define NP 500      // products
#define ED 128      // embedding dim

// ---------------- scratch (static __device__ — no allocations) ----------------
__device__ float  g_ts[(size_t)NF * NP];   // total_supplied [F, P], 200 MB
__device__ float  g_tmp[NP * ED];          // E @ B           [P, D]
__device__ float  g_att[NP * NP];          // relu(E B E^T)   [P, P]
__device__ double g_acc[2];                // [0]=sum(max(tc-inv,0)), [1]=sum(tc)

// ---------------- zero scratch ----------------
__global__ void k_zero() {
    long long idx = (long long)blockIdx.x * blockDim.x + threadIdx.x;
    long long n4  = (long long)NF * NP / 4;
    float4 z = make_float4(0.f, 0.f, 0.f, 0.f);
    float4* p = reinterpret_cast<float4*>(g_ts);
    long long stride = (long long)gridDim.x * blockDim.x;
    for (long long i = idx; i < n4; i += stride) p[i] = z;
    if (idx == 0) { g_acc[0] = 0.0; g_acc[1] = 0.0; }
}

// ---------------- edge scatter: TS[src, prod-NF] += max(raw_msg[:,0], 1) ----------------
__global__ void k_scatter(const int* __restrict__ src, const int* __restrict__ prod,
                          const float* __restrict__ raw, int E) {
    int e = blockIdx.x * blockDim.x + threadIdx.x;
    if (e >= E) return;
    float a = fmaxf(raw[(size_t)e * 4], 1.0f);
    int f = src[e];
    int p = prod[e] - NF;
    atomicAdd(&g_ts[(size_t)f * NP + p], a);
}

// ---------------- tmp = E @ B  ([P,D] = [P,D] x [D,D]) ----------------
__global__ void k_tmp(const float* __restrict__ E, const float* __restrict__ B) {
    __shared__ float se[ED];
    int p = blockIdx.x;
    int j = threadIdx.x;                 // 128 threads
    se[j] = E[p * ED + j];
    __syncthreads();
    float s = 0.f;
#pragma unroll 8
    for (int k = 0; k < ED; k++) s = fmaf(se[k], B[k * ED + j], s);
    g_tmp[p * ED + j] = s;
}

// ---------------- att = relu(tmp @ E^T)  ([P,P]) ----------------
__global__ void k_att(const float* __restrict__ E) {
    __shared__ float sT[16][ED + 1];
    __shared__ float sE[16][ED + 1];
    int p0 = blockIdx.y * 16, q0 = blockIdx.x * 16;
    int tid = threadIdx.x;               // 256 threads
    for (int i = tid; i < 16 * ED; i += 256) {
        int r = i / ED, c = i % ED;
        sT[r][c] = (p0 + r < NP) ? g_tmp[(p0 + r) * ED + c] : 0.f;
        sE[r][c] = (q0 + r < NP) ? E[(q0 + r) * ED + c] : 0.f;
    }
    __syncthreads();
    int tx = tid & 15, ty = tid >> 4;
    float s = 0.f;
#pragma unroll 8
    for (int k = 0; k < ED; k++) s = fmaf(sT[ty][k], sE[tx][k], s);
    int p = p0 + ty, q = q0 + tx;
    if (p < NP && q < NP) g_att[p * NP + q] = fmaxf(s, 0.f);
}

// ---------------- main GEMM (TS @ att) with fused epilogue reductions ----------------
// BM=128, BN=128, BK=16, 256 threads, 8x8 per-thread microtile.
#define BM 128
#define BN 128
#define BK 16

__global__ __launch_bounds__(256) void k_main(const float* __restrict__ inv) {
    __shared__ float As[BK][BM + 4];     // +4 pad: stride 132 floats, 16B-aligned rows
    __shared__ float Bs[BK][BN];

    const float* __restrict__ ts  = g_ts;
    const float* __restrict__ att = g_att;

    int bm = blockIdx.x * BM;
    int bn = blockIdx.y * BN;
    int tid = threadIdx.x;
    int tx = tid & 15, ty = tid >> 4;
    int rbase = ty * 8;                  // local row base
    int cbase = tx * 8;                  // local col base

    float acc[8][8];
#pragma unroll
    for (int i = 0; i < 8; i++)
#pragma unroll
        for (int j = 0; j < 8; j++) acc[i][j] = 0.f;

    for (int k0 = 0; k0 < NP; k0 += BK) {
        // A tile: 128 rows x 16 k, transposed store. Consecutive tids read
        // consecutive k within a row -> 64B coalesced segments.
#pragma unroll
        for (int i = tid; i < BM * BK; i += 256) {
            int m = i >> 4;
            int k = i & 15;
            int gm = bm + m, gk = k0 + k;
            As[k][m] = (gm < NF && gk < NP) ? ts[(size_t)gm * NP + gk] : 0.f;
        }
        // B tile: 16 k x 128 n, coalesced 128-float rows.
#pragma unroll
        for (int i = tid; i < BK * BN; i += 256) {
            int k = i >> 7;
            int n = i & 127;
            int gk = k0 + k, gn = bn + n;
            Bs[k][n] = (gk < NP && gn < NP) ? att[gk * NP + gn] : 0.f;
        }
        __syncthreads();

#pragma unroll
        for (int kk = 0; kk < BK; kk++) {
            float4 a0 = *reinterpret_cast<const float4*>(&As[kk][rbase]);
            float4 a1 = *reinterpret_cast<const float4*>(&As[kk][rbase + 4]);
            float4 b0 = *reinterpret_cast<const float4*>(&Bs[kk][cbase]);
            float4 b1 = *reinterpret_cast<const float4*>(&Bs[kk][cbase + 4]);
            float a[8] = {a0.x, a0.y, a0.z, a0.w, a1.x, a1.y, a1.z, a1.w};
            float b[8] = {b0.x, b0.y, b0.z, b0.w, b1.x, b1.y, b1.z, b1.w};
#pragma unroll
            for (int i = 0; i < 8; i++)
#pragma unroll
                for (int j = 0; j < 8; j++) acc[i][j] = fmaf(a[i], b[j], acc[i][j]);
        }
        __syncthreads();
    }

    // Fused epilogue: never write TC. diff = max(tc - inv, 0); accumulate both sums.
    float tD = 0.f, tC = 0.f;
#pragma unroll
    for (int i = 0; i < 8; i++) {
        int r = bm + rbase + i;
        if (r < NF) {
#pragma unroll
            for (int j = 0; j < 8; j++) {
                int c = bn + cbase + j;
                if (c < NP) {
                    float v = acc[i][j];
                    float iv = inv[(size_t)r * NP + c];
                    tC += v;
                    tD += fmaxf(v - iv, 0.f);
                }
            }
        }
    }

    // block reduction in double, then one atomic pair per block
    double dD = (double)tD, dC = (double)tC;
#pragma unroll
    for (int off = 16; off > 0; off >>= 1) {
        dD += __shfl_down_sync(0xFFFFFFFFu, dD, off);
        dC += __shfl_down_sync(0xFFFFFFFFu, dC, off);
    }
    __shared__ double sD[8], sC[8];
    int wid = tid >> 5, lid = tid & 31;
    if (lid == 0) { sD[wid] = dD; sC[wid] = dC; }
    __syncthreads();
    if (wid == 0) {
        double rD = (lid < 8) ? sD[lid] : 0.0;
        double rC = (lid < 8) ? sC[lid] : 0.0;
#pragma unroll
        for (int off = 4; off > 0; off >>= 1) {
            rD += __shfl_down_sync(0xFFFFFFFFu, rD, off);
            rC += __shfl_down_sync(0xFFFFFFFFu, rC, off);
        }
        if (lid == 0) {
            atomicAdd(&g_acc[0], rD);
            atomicAdd(&g_acc[1], rC);
        }
    }
}

// ---------------- finalize: 3 scalars ----------------
__global__ void k_fin(float* __restrict__ out, int E) {
    double D = g_acc[0] * 10.0;   // DEBT_PENALTY
    double C = g_acc[1];          // CONSUMPTION_REWARD = 1
    double n = (double)E;
    out[0] = (float)((D - C) / n);
    out[1] = (float)(D / n);
    out[2] = (float)(C / n);
}

// ---------------- launch ----------------
extern "C" void kernel_launch(void* const* d_in, const int* in_sizes, int n_in,
                              void* d_out, int out_size) {
    const int*   src  = (const int*)d_in[0];
    // d_in[1] = dst — unused by the reference
    const int*   prod = (const int*)d_in[2];
    const float* raw  = (const float*)d_in[3];
    const float* emb  = (const float*)d_in[4];
    const float* bil  = (const float*)d_in[5];
    const float* inv  = (const float*)d_in[6];
    float* out = (float*)d_out;
    int E = in_sizes[0];

    k_zero<<<2048, 256>>>();
    k_scatter<<<(E + 255) / 256, 256>>>(src, prod, raw, E);
    k_tmp<<<NP, ED>>>(emb, bil);
    k_att<<<dim3((NP + 15) / 16, (NP + 15) / 16), 256>>>(emb);
    k_main<<<dim3((NF + BM - 1) / BM, (NP + BN - 1) / BN), 256>>>(inv);
    k_fin<<<1, 1>>>(out, E);
}

// round 2
// speedup vs baseline: 2.3373x; 2.3373x over previous
#include <cuda_runtime.h>
#include <cuda_bf16.h>
#include <math.h>
#include <stdint.h>

// Problem constants (fixed by the dataset)
#define NF 100000   // firms
#define NP 500      // products
#define ED 128      // embedding dim
#define KPAD 512    // padded K / N for the big GEMM

// ---------------- scratch (static __device__ — no allocations) ----------------
__device__ float         g_ts[(size_t)NF * NP];       // total_supplied fp32 [F, P], 200 MB
__device__ __nv_bfloat16 g_tsb[(size_t)NF * KPAD];    // TS in bf16, K padded to 512, 100 MB
__device__ float         g_tmp[NP * ED];              // E @ B           [P, D]
__device__ __nv_bfloat16 g_attb[KPAD * KPAD];         // relu(E B E^T) TRANSPOSED bf16: [n][k]
__device__ double        g_acc[2];                    // [0]=sum(max(tc-inv,0)), [1]=sum(tc)

__device__ __forceinline__ uint32_t s2u(const void* p) {
    return (uint32_t)__cvta_generic_to_shared(p);
}

// ---------------- zero scratch ----------------
__global__ void k_zero() {
    long long idx = (long long)blockIdx.x * blockDim.x + threadIdx.x;
    long long stride = (long long)gridDim.x * blockDim.x;
    float4 z = make_float4(0.f, 0.f, 0.f, 0.f);
    // TS fp32 (200 MB)
    {
        long long n4 = (long long)NF * NP / 4;
        float4* p = reinterpret_cast<float4*>(g_ts);
        for (long long i = idx; i < n4; i += stride) p[i] = z;
    }
    // att bf16 transposed (512 KB) — padding must be zero
    {
        long long n4 = (long long)KPAD * KPAD * 2 / 16;
        float4* p = reinterpret_cast<float4*>(g_attb);
        for (long long i = idx; i < n4; i += stride) p[i] = z;
    }
    if (idx == 0) { g_acc[0] = 0.0; g_acc[1] = 0.0; }
}

// ---------------- edge scatter: TS[src, prod-NF] += max(raw_msg[:,0], 1) ----------------
__global__ void k_scatter(const int* __restrict__ src, const int* __restrict__ prod,
                          const float* __restrict__ raw, int E) {
    int e = blockIdx.x * blockDim.x + threadIdx.x;
    if (e >= E) return;
    float a = fmaxf(raw[(size_t)e * 4], 1.0f);
    int f = src[e];
    int p = prod[e] - NF;
    atomicAdd(&g_ts[(size_t)f * NP + p], a);
}

// ---------------- convert TS fp32 -> bf16 with K padded to 512 ----------------
__global__ void k_conv() {
    long long j = (long long)blockIdx.x * blockDim.x + threadIdx.x;
    long long tot = (long long)NF * (KPAD / 8);   // one thread per 8 halves
    if (j >= tot) return;
    long long f = j >> 6;        // KPAD/8 = 64 chunks per row
    int ch = (int)(j & 63);
    int k = ch * 8;
    __nv_bfloat16 o[8];
#pragma unroll
    for (int i = 0; i < 8; i++) {
        int kk = k + i;
        o[i] = (kk < NP) ? __float2bfloat16(g_ts[f * NP + kk]) : __float2bfloat16(0.f);
    }
    *reinterpret_cast<uint4*>(&g_tsb[f * KPAD + k]) = *reinterpret_cast<uint4*>(o);
}

// ---------------- tmp = E @ B  ([P,D] = [P,D] x [D,D]) ----------------
__global__ void k_tmp(const float* __restrict__ E, const float* __restrict__ B) {
    __shared__ float se[ED];
    int p = blockIdx.x;
    int j = threadIdx.x;                 // 128 threads
    se[j] = E[p * ED + j];
    __syncthreads();
    float s = 0.f;
#pragma unroll 8
    for (int k = 0; k < ED; k++) s = fmaf(se[k], B[k * ED + j], s);
    g_tmp[p * ED + j] = s;
}

// ---------------- att_t = relu(tmp @ E^T)^T in bf16 ([n][k] layout) ----------------
__global__ void k_att(const float* __restrict__ E) {
    __shared__ float sT[16][ED + 1];
    __shared__ float sE[16][ED + 1];
    int p0 = blockIdx.y * 16, q0 = blockIdx.x * 16;
    int tid = threadIdx.x;               // 256 threads
    for (int i = tid; i < 16 * ED; i += 256) {
        int r = i / ED, c = i % ED;
        sT[r][c] = (p0 + r < NP) ? g_tmp[(p0 + r) * ED + c] : 0.f;
        sE[r][c] = (q0 + r < NP) ? E[(q0 + r) * ED + c] : 0.f;
    }
    __syncthreads();
    int tx = tid & 15, ty = tid >> 4;
    float s = 0.f;
#pragma unroll 8
    for (int k = 0; k < ED; k++) s = fmaf(sT[ty][k], sE[tx][k], s);
    int p = p0 + ty, q = q0 + tx;        // p = k index, q = n index
    if (p < NP && q < NP)
        g_attb[q * KPAD + p] = __float2bfloat16(fmaxf(s, 0.f));
}

// ---------------- main GEMM (TS @ att) on tensor cores, fused epilogue ----------------
// BM=128, BN=128, BK=32, 256 threads = 8 warps (4x2), warp tile 32x64.
// mma.sync.m16n8k16 bf16 -> fp32.
#define BM 128
#define BN 128
#define BK 32
#define STR 40   // smem row stride in halves (80 B: 16B-aligned, ldmatrix conflict-free)

__global__ __launch_bounds__(256) void k_gemm(const float* __restrict__ inv) {
    __shared__ __nv_bfloat16 As[BM * STR];
    __shared__ __nv_bfloat16 Bs[BN * STR];

    const int tid  = threadIdx.x;
    const int lane = tid & 31;
    const int warp = tid >> 5;
    const int wm = warp >> 1;            // 0..3
    const int wn = warp & 1;             // 0..1
    const int m_w = wm * 32;
    const int n_w = wn * 64;
    const int bm = blockIdx.x * BM;
    const int bn = blockIdx.y * BN;

    // ldmatrix source row/col within a 16x16 block
    const int lrow = lane & 15;
    const int lk8  = (lane >> 4) << 3;

    float c[2][8][4];
#pragma unroll
    for (int mt = 0; mt < 2; mt++)
#pragma unroll
        for (int nt = 0; nt < 8; nt++)
#pragma unroll
            for (int r = 0; r < 4; r++) c[mt][nt][r] = 0.f;

    for (int k0 = 0; k0 < KPAD; k0 += BK) {
        // A tile: 128 rows x 32 halves (64 B/row); 16B per thread, 2 passes
#pragma unroll
        for (int p = 0; p < 2; p++) {
            int i = tid + p * 256;
            int r = i >> 2, ch = i & 3;
            uint4 v = make_uint4(0u, 0u, 0u, 0u);
            long long gr = bm + r;
            if (gr < NF)
                v = *reinterpret_cast<const uint4*>(&g_tsb[(size_t)gr * KPAD + k0 + ch * 8]);
            *reinterpret_cast<uint4*>(&As[r * STR + ch * 8]) = v;
        }
        // B tile: 128 n-rows x 32 k-halves from transposed att (fully padded)
#pragma unroll
        for (int p = 0; p < 2; p++) {
            int i = tid + p * 256;
            int r = i >> 2, ch = i & 3;
            uint4 v = *reinterpret_cast<const uint4*>(&g_attb[(size_t)(bn + r) * KPAD + k0 + ch * 8]);
            *reinterpret_cast<uint4*>(&Bs[r * STR + ch * 8]) = v;
        }
        __syncthreads();

#pragma unroll
        for (int ks = 0; ks < 2; ks++) {
            const int kk = ks * 16;
            // A fragments: 2 m16 tiles, ldmatrix.x4 each
            uint32_t a[2][4];
#pragma unroll
            for (int mt = 0; mt < 2; mt++) {
                uint32_t addr = s2u(&As[(m_w + mt * 16 + lrow) * STR + kk + lk8]);
                asm volatile("ldmatrix.sync.aligned.m8n8.x4.shared.b16 {%0,%1,%2,%3}, [%4];"
                             : "=r"(a[mt][0]), "=r"(a[mt][1]), "=r"(a[mt][2]), "=r"(a[mt][3])
                             : "r"(addr));
            }
            // B fragments: 8 n8 tiles, one ldmatrix.x4 covers two adjacent n8 tiles
            uint32_t b[8][2];
#pragma unroll
            for (int np = 0; np < 4; np++) {
                uint32_t addr = s2u(&Bs[(n_w + np * 16 + lrow) * STR + kk + lk8]);
                uint32_t r0, r1, r2, r3;
                asm volatile("ldmatrix.sync.aligned.m8n8.x4.shared.b16 {%0,%1,%2,%3}, [%4];"
                             : "=r"(r0), "=r"(r1), "=r"(r2), "=r"(r3)
                             : "r"(addr));
                b[np * 2][0]     = r0;   // n-tile even, k 0-7
                b[np * 2 + 1][0] = r1;   // n-tile odd,  k 0-7
                b[np * 2][1]     = r2;   // n-tile even, k 8-15
                b[np * 2 + 1][1] = r3;   // n-tile odd,  k 8-15
            }
#pragma unroll
            for (int mt = 0; mt < 2; mt++)
#pragma unroll
                for (int nt = 0; nt < 8; nt++) {
                    asm volatile(
                        "mma.sync.aligned.m16n8k16.row.col.f32.bf16.bf16.f32 "
                        "{%0,%1,%2,%3}, {%4,%5,%6,%7}, {%8,%9}, {%0,%1,%2,%3};"
                        : "+f"(c[mt][nt][0]), "+f"(c[mt][nt][1]),
                          "+f"(c[mt][nt][2]), "+f"(c[mt][nt][3])
                        : "r"(a[mt][0]), "r"(a[mt][1]), "r"(a[mt][2]), "r"(a[mt][3]),
                          "r"(b[nt][0]), "r"(b[nt][1]));
                }
        }
        __syncthreads();
    }

    // Fused epilogue: never write TC. Fragment layout: (row g, cols 2t,2t+1) and (row g+8).
    const int g = lane >> 2;
    const int t = lane & 3;
    float tD = 0.f, tC = 0.f;
#pragma unroll
    for (int mt = 0; mt < 2; mt++) {
        int r0 = bm + m_w + mt * 16 + g;
        int r1 = r0 + 8;
#pragma unroll
        for (int nt = 0; nt < 8; nt++) {
            int c0 = bn + n_w + nt * 8 + 2 * t;
            int c1 = c0 + 1;
            if (r0 < NF) {
                if (c0 < NP) {
                    float v = c[mt][nt][0];
                    tC += v; tD += fmaxf(v - inv[(size_t)r0 * NP + c0], 0.f);
                }
                if (c1 < NP) {
                    float v = c[mt][nt][1];
                    tC += v; tD += fmaxf(v - inv[(size_t)r0 * NP + c1], 0.f);
                }
            }
            if (r1 < NF) {
                if (c0 < NP) {
                    float v = c[mt][nt][2];
                    tC += v; tD += fmaxf(v - inv[(size_t)r1 * NP + c0], 0.f);
                }
                if (c1 < NP) {
                    float v = c[mt][nt][3];
                    tC += v; tD += fmaxf(v - inv[(size_t)r1 * NP + c1], 0.f);
                }
            }
        }
    }

    // block reduction in double, one atomic pair per block
    double dD = (double)tD, dC = (double)tC;
#pragma unroll
    for (int off = 16; off > 0; off >>= 1) {
        dD += __shfl_down_sync(0xFFFFFFFFu, dD, off);
        dC += __shfl_down_sync(0xFFFFFFFFu, dC, off);
    }
    __shared__ double sD[8], sC[8];
    int wid = tid >> 5, lid = tid & 31;
    if (lid == 0) { sD[wid] = dD; sC[wid] = dC; }
    __syncthreads();
    if (wid == 0) {
        double rD = (lid < 8) ? sD[lid] : 0.0;
        double rC = (lid < 8) ? sC[lid] : 0.0;
#pragma unroll
        for (int off = 4; off > 0; off >>= 1) {
            rD += __shfl_down_sync(0xFFFFFFFFu, rD, off);
            rC += __shfl_down_sync(0xFFFFFFFFu, rC, off);
        }
        if (lid == 0) {
            atomicAdd(&g_acc[0], rD);
            atomicAdd(&g_acc[1], rC);
        }
    }
}

// ---------------- finalize: 3 scalars ----------------
__global__ void k_fin(float* __restrict__ out, int E) {
    double D = g_acc[0] * 10.0;   // DEBT_PENALTY
    double C = g_acc[1];          // CONSUMPTION_REWARD = 1
    double n = (double)E;
    out[0] = (float)((D - C) / n);
    out[1] = (float)(D / n);
    out[2] = (float)(C / n);
}

// ---------------- launch ----------------
extern "C" void kernel_launch(void* const* d_in, const int* in_sizes, int n_in,
                              void* d_out, int out_size) {
    const int*   src  = (const int*)d_in[0];
    // d_in[1] = dst — unused by the reference
    const int*   prod = (const int*)d_in[2];
    const float* raw  = (const float*)d_in[3];
    const float* emb  = (const float*)d_in[4];
    const float* bil  = (const float*)d_in[5];
    const float* inv  = (const float*)d_in[6];
    float* out = (float*)d_out;
    int E = in_sizes[0];

    k_zero<<<2048, 256>>>();
    k_scatter<<<(E + 255) / 256, 256>>>(src, prod, raw, E);
    {
        long long tot = (long long)NF * (KPAD / 8);
        k_conv<<<(unsigned)((tot + 255) / 256), 256>>>();
    }
    k_tmp<<<NP, ED>>>(emb, bil);
    k_att<<<dim3((KPAD + 15) / 16, (KPAD + 15) / 16), 256>>>(emb);
    k_gemm<<<dim3((NF + BM - 1) / BM, (KPAD + BN - 1) / BN), 256>>>(inv);
    k_fin<<<1, 1>>>(out, E);
}

// round 3
// speedup vs baseline: 3.3095x; 1.4160x over previous
#include <cuda_runtime.h>
#include <cuda_bf16.h>
#include <math.h>
#include <stdint.h>

// Problem constants (fixed by the dataset)
#define NF 100000   // firms
#define NP 500      // products
#define ED 128      // embedding dim
#define KPAD 512    // padded K / N for the big GEMM

// ---------------- scratch (static __device__ — no allocations) ----------------
__device__ __nv_bfloat16 g_tsb[(size_t)NF * KPAD];    // TS in bf16, K padded to 512, ~100 MB
__device__ float         g_tmp[NP * ED];              // E @ B           [P, D]
__device__ __nv_bfloat16 g_attb[KPAD * KPAD];         // relu(E B E^T) TRANSPOSED bf16: [n][k]
__device__ double        g_acc[2];                    // [0]=sum(max(tc-inv,0)), [1]=sum(tc)

__device__ __forceinline__ uint32_t s2u(const void* p) {
    return (uint32_t)__cvta_generic_to_shared(p);
}

// ---------------- zero scratch ----------------
__global__ void k_zero() {
    long long idx = (long long)blockIdx.x * blockDim.x + threadIdx.x;
    long long stride = (long long)gridDim.x * blockDim.x;
    uint4 z = make_uint4(0u, 0u, 0u, 0u);
    // TS bf16 (~100 MB), includes the zero K-padding cols 500..511
    {
        long long n16 = (long long)NF * KPAD * 2 / 16;
        uint4* p = reinterpret_cast<uint4*>(g_tsb);
        for (long long i = idx; i < n16; i += stride) p[i] = z;
    }
    // att bf16 transposed (512 KB) — padding must be zero
    {
        long long n16 = (long long)KPAD * KPAD * 2 / 16;
        uint4* p = reinterpret_cast<uint4*>(g_attb);
        for (long long i = idx; i < n16; i += stride) p[i] = z;
    }
    if (idx == 0) { g_acc[0] = 0.0; g_acc[1] = 0.0; }
}

// ---- edge scatter: TSb[src, prod-NF] += max(raw_msg[:,0], 1), bf16 atomics ----
__global__ void k_scatter(const int* __restrict__ src, const int* __restrict__ prod,
                          const float* __restrict__ raw, int E) {
    int e = blockIdx.x * blockDim.x + threadIdx.x;
    if (e >= E) return;
    float a = fmaxf(raw[(size_t)e * 4], 1.0f);
    int f = src[e];
    int p = prod[e] - NF;
    size_t idx = (size_t)f * KPAD + p;
    __nv_bfloat16 hv = __float2bfloat16(a);
    __nv_bfloat16 hz = __float2bfloat16(0.f);
    __nv_bfloat162 v = (idx & 1) ? __nv_bfloat162(hz, hv) : __nv_bfloat162(hv, hz);
    atomicAdd(reinterpret_cast<__nv_bfloat162*>(&g_tsb[idx & ~(size_t)1]), v);
}

// ---------------- tmp = E @ B  ([P,D] = [P,D] x [D,D]) ----------------
__global__ void k_tmp(const float* __restrict__ E, const float* __restrict__ B) {
    __shared__ float se[ED];
    int p = blockIdx.x;
    int j = threadIdx.x;                 // 128 threads
    se[j] = E[p * ED + j];
    __syncthreads();
    float s0 = 0.f, s1 = 0.f, s2 = 0.f, s3 = 0.f;
#pragma unroll
    for (int k = 0; k < ED; k += 4) {
        s0 = fmaf(se[k + 0], B[(k + 0) * ED + j], s0);
        s1 = fmaf(se[k + 1], B[(k + 1) * ED + j], s1);
        s2 = fmaf(se[k + 2], B[(k + 2) * ED + j], s2);
        s3 = fmaf(se[k + 3], B[(k + 3) * ED + j], s3);
    }
    g_tmp[p * ED + j] = (s0 + s1) + (s2 + s3);
}

// ---------------- att_t = relu(tmp @ E^T)^T in bf16 ([n][k] layout) ----------------
__global__ void k_att(const float* __restrict__ E) {
    __shared__ float sT[16][ED + 1];
    __shared__ float sE[16][ED + 1];
    int p0 = blockIdx.y * 16, q0 = blockIdx.x * 16;
    int tid = threadIdx.x;               // 256 threads
    for (int i = tid; i < 16 * ED; i += 256) {
        int r = i / ED, c = i % ED;
        sT[r][c] = (p0 + r < NP) ? g_tmp[(p0 + r) * ED + c] : 0.f;
        sE[r][c] = (q0 + r < NP) ? E[(q0 + r) * ED + c] : 0.f;
    }
    __syncthreads();
    int tx = tid & 15, ty = tid >> 4;
    float s = 0.f;
#pragma unroll 8
    for (int k = 0; k < ED; k++) s = fmaf(sT[ty][k], sE[tx][k], s);
    int p = p0 + ty, q = q0 + tx;        // p = k index, q = n index
    if (p < NP && q < NP)
        g_attb[q * KPAD + p] = __float2bfloat16(fmaxf(s, 0.f));
}

// ---------------- main GEMM (TS @ att) on tensor cores, cp.async pipelined ----------------
// BM=128, BN=128, BK=32, 256 threads = 8 warps (4x2), warp tile 32x64.
// mma.sync.m16n8k16 bf16 -> fp32, 2-stage cp.async double buffer.
#define BM 128
#define BN 128
#define BK 32
#define NK (KPAD / BK)   // 16 k-steps
#define STR 40           // smem row stride in halves (80 B: 16B-aligned, ldmatrix conflict-free)

__global__ __launch_bounds__(256) void k_gemm(const float* __restrict__ inv) {
    __shared__ __nv_bfloat16 As[2][BM * STR];
    __shared__ __nv_bfloat16 Bs[2][BN * STR];

    const int tid  = threadIdx.x;
    const int lane = tid & 31;
    const int warp = tid >> 5;
    const int wm = warp >> 1;            // 0..3
    const int wn = warp & 1;             // 0..1
    const int m_w = wm * 32;
    const int n_w = wn * 64;
    const int bn = blockIdx.x * BN;      // x = n-tile (4): concurrent blocks share A via L2
    const int bm = blockIdx.y * BM;      // y = m-tile (782)

    // per-thread cp.async coords: chunk c = tid + p*256, row = c>>2, 8-half col chunk = c&3
    const int lrow = lane & 15;          // ldmatrix row within 16x16 block
    const int lk8  = (lane >> 4) << 3;   // ldmatrix k-offset (0 or 8)

    float acc[2][8][4];
#pragma unroll
    for (int mt = 0; mt < 2; mt++)
#pragma unroll
        for (int nt = 0; nt < 8; nt++)
#pragma unroll
            for (int r = 0; r < 4; r++) acc[mt][nt][r] = 0.f;

    auto issue = [&](int stage, int k0) {
#pragma unroll
        for (int p = 0; p < 2; p++) {
            int c = tid + p * 256;
            int r = c >> 2, ch = c & 3;
            // A: zero-fill rows beyond NF via src-size=0
            long long gr = (long long)bm + r;
            const void* srcA = &g_tsb[(size_t)gr * KPAD + k0 + ch * 8];
            uint32_t dstA = s2u(&As[stage][r * STR + ch * 8]);
            int szA = (gr < NF) ? 16 : 0;
            asm volatile("cp.async.cg.shared.global [%0], [%1], 16, %2;\n"
                         :: "r"(dstA), "l"(srcA), "r"(szA));
            // B: attb fully sized [512][512], no guard needed
            const void* srcB = &g_attb[(size_t)(bn + r) * KPAD + k0 + ch * 8];
            uint32_t dstB = s2u(&Bs[stage][r * STR + ch * 8]);
            asm volatile("cp.async.cg.shared.global [%0], [%1], 16;\n"
                         :: "r"(dstB), "l"(srcB));
        }
        asm volatile("cp.async.commit_group;\n");
    };

    issue(0, 0);

    for (int kt = 0; kt < NK; kt++) {
        asm volatile("cp.async.wait_group 0;\n");
        __syncthreads();
        // prefetch next k-step into the other buffer while computing this one
        if (kt + 1 < NK) issue((kt + 1) & 1, (kt + 1) * BK);

        const __nv_bfloat16* Ast = As[kt & 1];
        const __nv_bfloat16* Bst = Bs[kt & 1];
#pragma unroll
        for (int ks = 0; ks < 2; ks++) {
            const int kk = ks * 16;
            uint32_t a[2][4];
#pragma unroll
            for (int mt = 0; mt < 2; mt++) {
                uint32_t addr = s2u(&Ast[(m_w + mt * 16 + lrow) * STR + kk + lk8]);
                asm volatile("ldmatrix.sync.aligned.m8n8.x4.shared.b16 {%0,%1,%2,%3}, [%4];"
                             : "=r"(a[mt][0]), "=r"(a[mt][1]), "=r"(a[mt][2]), "=r"(a[mt][3])
                             : "r"(addr));
            }
            uint32_t b[8][2];
#pragma unroll
            for (int np = 0; np < 4; np++) {
                uint32_t addr = s2u(&Bst[(n_w + np * 16 + lrow) * STR + kk + lk8]);
                uint32_t r0, r1, r2, r3;
                asm volatile("ldmatrix.sync.aligned.m8n8.x4.shared.b16 {%0,%1,%2,%3}, [%4];"
                             : "=r"(r0), "=r"(r1), "=r"(r2), "=r"(r3)
                             : "r"(addr));
                b[np * 2][0]     = r0;
                b[np * 2 + 1][0] = r1;
                b[np * 2][1]     = r2;
                b[np * 2 + 1][1] = r3;
            }
#pragma unroll
            for (int mt = 0; mt < 2; mt++)
#pragma unroll
                for (int nt = 0; nt < 8; nt++) {
                    asm volatile(
                        "mma.sync.aligned.m16n8k16.row.col.f32.bf16.bf16.f32 "
                        "{%0,%1,%2,%3}, {%4,%5,%6,%7}, {%8,%9}, {%0,%1,%2,%3};"
                        : "+f"(acc[mt][nt][0]), "+f"(acc[mt][nt][1]),
                          "+f"(acc[mt][nt][2]), "+f"(acc[mt][nt][3])
                        : "r"(a[mt][0]), "r"(a[mt][1]), "r"(a[mt][2]), "r"(a[mt][3]),
                          "r"(b[nt][0]), "r"(b[nt][1]));
                }
        }
        __syncthreads();
    }

    // Fused epilogue: never write TC. Fragment layout: (row g, cols 2t,2t+1) and (row g+8).
    const int g = lane >> 2;
    const int t = lane & 3;
    float tD = 0.f, tC = 0.f;
#pragma unroll
    for (int mt = 0; mt < 2; mt++) {
        int r0 = bm + m_w + mt * 16 + g;
        int r1 = r0 + 8;
#pragma unroll
        for (int nt = 0; nt < 8; nt++) {
            int c0 = bn + n_w + nt * 8 + 2 * t;
            int c1 = c0 + 1;
            if (r0 < NF) {
                if (c0 < NP) {
                    float v = acc[mt][nt][0];
                    tC += v; tD += fmaxf(v - inv[(size_t)r0 * NP + c0], 0.f);
                }
                if (c1 < NP) {
                    float v = acc[mt][nt][1];
                    tC += v; tD += fmaxf(v - inv[(size_t)r0 * NP + c1], 0.f);
                }
            }
            if (r1 < NF) {
                if (c0 < NP) {
                    float v = acc[mt][nt][2];
                    tC += v; tD += fmaxf(v - inv[(size_t)r1 * NP + c0], 0.f);
                }
                if (c1 < NP) {
                    float v = acc[mt][nt][3];
                    tC += v; tD += fmaxf(v - inv[(size_t)r1 * NP + c1], 0.f);
                }
            }
        }
    }

    // block reduction in double, one atomic pair per block
    double dD = (double)tD, dC = (double)tC;
#pragma unroll
    for (int off = 16; off > 0; off >>= 1) {
        dD += __shfl_down_sync(0xFFFFFFFFu, dD, off);
        dC += __shfl_down_sync(0xFFFFFFFFu, dC, off);
    }
    __shared__ double sD[8], sC[8];
    int wid = tid >> 5, lid = tid & 31;
    if (lid == 0) { sD[wid] = dD; sC[wid] = dC; }
    __syncthreads();
    if (wid == 0) {
        double rD = (lid < 8) ? sD[lid] : 0.0;
        double rC = (lid < 8) ? sC[lid] : 0.0;
#pragma unroll
        for (int off = 4; off > 0; off >>= 1) {
            rD += __shfl_down_sync(0xFFFFFFFFu, rD, off);
            rC += __shfl_down_sync(0xFFFFFFFFu, rC, off);
        }
        if (lid == 0) {
            atomicAdd(&g_acc[0], rD);
            atomicAdd(&g_acc[1], rC);
        }
    }
}

// ---------------- finalize: 3 scalars ----------------
__global__ void k_fin(float* __restrict__ out, int E) {
    double D = g_acc[0] * 10.0;   // DEBT_PENALTY
    double C = g_acc[1];          // CONSUMPTION_REWARD = 1
    double n = (double)E;
    out[0] = (float)((D - C) / n);
    out[1] = (float)(D / n);
    out[2] = (float)(C / n);
}

// ---------------- launch ----------------
extern "C" void kernel_launch(void* const* d_in, const int* in_sizes, int n_in,
                              void* d_out, int out_size) {
    const int*   src  = (const int*)d_in[0];
    // d_in[1] = dst — unused by the reference
    const int*   prod = (const int*)d_in[2];
    const float* raw  = (const float*)d_in[3];
    const float* emb  = (const float*)d_in[4];
    const float* bil  = (const float*)d_in[5];
    const float* inv  = (const float*)d_in[6];
    float* out = (float*)d_out;
    int E = in_sizes[0];

    k_zero<<<4096, 256>>>();
    k_scatter<<<(E + 255) / 256, 256>>>(src, prod, raw, E);
    k_tmp<<<NP, ED>>>(emb, bil);
    k_att<<<dim3((KPAD + 15) / 16, (KPAD + 15) / 16), 256>>>(emb);
    k_gemm<<<dim3(KPAD / BN, (NF + BM - 1) / BM), 256>>>(inv);
    k_fin<<<1, 1>>>(out, E);
}